// round 3
// baseline (speedup 1.0000x reference)
#include <cuda_runtime.h>
#include <math.h>

// ---------------------------------------------------------------------------
// One big scratch arena (no allocations allowed -> __device__ global).
// All offsets in floats.
// ---------------------------------------------------------------------------
constexpr int OX0  = 0;          // 2*4*64^3      = 2097152  masked input
constexpr int OZ1  = 2097152;    // 2*32*32^3     = 2097152
constexpr int OZ2  = 4194304;    // 2*64*16^3     = 524288
constexpr int OZ3  = 4718592;    // 2*128*8^3     = 131072
constexpr int OZ4  = 4849664;    // 2*128*16^3    = 1048576
constexpr int OZ5  = 5898240;    // 2*64*32^3     = 4194304
constexpr int OM0  = 10092544;   // 2*64^3        = 524288
constexpr int OM1  = 10616832;   // 2*32^3        = 65536
constexpr int OM2  = 10682368;   // 2*16^3        = 8192
constexpr int OM3  = 10690560;   // 2*8^3         = 1024
constexpr int OM4  = 10691584;   // 2*16^3        = 8192
constexpr int OM5  = 10699776;   // 2*32^3        = 65536
constexpr int OW1  = 10765312;   // 32*4*64       = 8192
constexpr int OW2  = 10773504;   // 64*32*64      = 131072
constexpr int OW3  = 10904576;   // 128*64*64     = 524288
constexpr int OTW1 = 11428864;   // 128*128*64    = 1048576
constexpr int OTW2 = 12477440;   // 64*128*64     = 524288
constexpr int OFW  = 13001728;   // 64*32         = 2048
constexpr int OST  = 13003776;   // 5*260 stats (sum[CO], sumsq[CO], cnt)
constexpr int OSC  = 13005076;   // 5*128 scale
constexpr int OSH  = 13005716;   // 5*128 shift
constexpr int TOT_SCRATCH = 13006848;

__device__ float g_scratch[TOT_SCRATCH];

// ---------------------------------------------------------------------------
// Small utility kernels
// ---------------------------------------------------------------------------
__global__ void k_zero(float* __restrict__ p, int n) {
    int i = blockIdx.x * 256 + threadIdx.x;
    if (i < n) p[i] = 0.f;
}

// x0 = feat * (mask > 0.5); m0 = (mask > 0.5)
__global__ void k_pre(const float* __restrict__ feat, const float* __restrict__ mask,
                      float* __restrict__ x0, float* __restrict__ m0) {
    int v = blockIdx.x * 256 + threadIdx.x;            // 0 .. 2*64^3-1
    float m = mask[v] > 0.5f ? 1.f : 0.f;
    m0[v] = m;
    int b = v >> 18;
    int r = v & 262143;
#pragma unroll
    for (int c = 0; c < 4; c++)
        x0[(b * 4 + c) * 262144 + r] = feat[(b * 4 + c) * 262144 + r] * m;
}

// wT[(t*CI+ci)*CO+co] = w[(co*CI+ci)*64+t]
__global__ void k_transpose(const float* __restrict__ w, float* __restrict__ wT,
                            int CI, int CO) {
    int idx = blockIdx.x * 256 + threadIdx.x;
    if (idx >= CO * CI * 64) return;
    int t  = idx & 63;
    int ci = (idx >> 6) % CI;
    int co = idx / (64 * CI);
    wT[(t * CI + ci) * CO + co] = w[idx];
}

// fwT[ci*32+co] = fw[co*64+ci]
__global__ void k_transpose_head(const float* __restrict__ fw, float* __restrict__ fwT) {
    int idx = blockIdx.x * 256 + threadIdx.x;          // 2048
    if (idx >= 2048) return;
    int co = idx / 64;
    int ci = idx % 64;
    fwT[ci * 32 + co] = fw[idx];
}

// ---------------------------------------------------------------------------
// Mask dilation (forward conv footprint, k=4 s=2 p=1) + active count
// ---------------------------------------------------------------------------
template <int DI, int DO>
__global__ void k_maskd_fwd(const float* __restrict__ mi, float* __restrict__ mo,
                            float* __restrict__ cnt) {
    const int DO3 = DO * DO * DO, DI2 = DI * DI, DI3 = DI * DI * DI;
    int v = blockIdx.x * 256 + threadIdx.x;
    int b = v / DO3, r = v % DO3;
    int oz = r / (DO * DO), oy = (r / DO) % DO, ox = r % DO;
    float m = 0.f;
    for (int tz = 0; tz < 4; tz++) {
        int iz = 2 * oz - 1 + tz;
        if ((unsigned)iz >= DI) continue;
        for (int ty = 0; ty < 4; ty++) {
            int iy = 2 * oy - 1 + ty;
            if ((unsigned)iy >= DI) continue;
            const float* p = mi + b * DI3 + iz * DI2 + iy * DI;
            for (int tx = 0; tx < 4; tx++) {
                int ix = 2 * ox - 1 + tx;
                if ((unsigned)ix < DI) m += p[ix];
            }
        }
    }
    float act = m > 0.f ? 1.f : 0.f;
    mo[v] = act;
    float s = act;
    for (int o = 16; o; o >>= 1) s += __shfl_xor_sync(0xffffffffu, s, o);
    if ((threadIdx.x & 31) == 0) atomicAdd(cnt, s);
}

// Mask dilation (transpose conv footprint, k=4 s=2 p=1) + active count
template <int DI, int DO>
__global__ void k_maskd_t(const float* __restrict__ mi, float* __restrict__ mo,
                          float* __restrict__ cnt) {
    const int DO3 = DO * DO * DO, DI2 = DI * DI, DI3 = DI * DI * DI;
    int v = blockIdx.x * 256 + threadIdx.x;
    int b = v / DO3, r = v % DO3;
    int oz = r / (DO * DO), oy = (r / DO) % DO, ox = r % DO;
    int izl[2], iyl[2], ixl[2];
    izl[0] = oz >> 1; izl[1] = (oz & 1) ? (oz >> 1) + 1 : (oz >> 1) - 1;
    iyl[0] = oy >> 1; iyl[1] = (oy & 1) ? (oy >> 1) + 1 : (oy >> 1) - 1;
    ixl[0] = ox >> 1; ixl[1] = (ox & 1) ? (ox >> 1) + 1 : (ox >> 1) - 1;
    float m = 0.f;
#pragma unroll
    for (int jz = 0; jz < 2; jz++) {
        int iz = izl[jz];
        if ((unsigned)iz >= DI) continue;
#pragma unroll
        for (int jy = 0; jy < 2; jy++) {
            int iy = iyl[jy];
            if ((unsigned)iy >= DI) continue;
#pragma unroll
            for (int jx = 0; jx < 2; jx++) {
                int ix = ixl[jx];
                if ((unsigned)ix < DI) m += mi[b * DI3 + iz * DI2 + iy * DI + ix];
            }
        }
    }
    float act = m > 0.f ? 1.f : 0.f;
    mo[v] = act;
    float s = act;
    for (int o = 16; o; o >>= 1) s += __shfl_xor_sync(0xffffffffu, s, o);
    if ((threadIdx.x & 31) == 0) atomicAdd(cnt, s);
}

// ---------------------------------------------------------------------------
// Forward conv k=4 s=2 p=1, + bias, * dilated mask, LeakyReLU, stats
// Thread = 1 output voxel x 8 consecutive co. Weights staged per (tz,ty) slab.
// ---------------------------------------------------------------------------
template <int CI, int CO, int DI, int DO>
__global__ void __launch_bounds__(256) k_conv_fwd(
    const float* __restrict__ x, const float* __restrict__ wT,
    const float* __restrict__ bias, const float* __restrict__ mo,
    float* __restrict__ z, float* __restrict__ stats) {
    __shared__ __align__(16) float sw[4 * CI * 8];
    __shared__ float ssum[8], ssq[8];
    const int DO3 = DO * DO * DO, DI3 = DI * DI * DI, DI2 = DI * DI;
    const int co0 = blockIdx.y * 8;
    const int v = blockIdx.x * 256 + threadIdx.x;
    const int b = v / DO3, r = v % DO3;
    const int oz = r / (DO * DO), oy = (r / DO) % DO, ox = r % DO;
    float acc[8];
#pragma unroll
    for (int k = 0; k < 8; k++) acc[k] = 0.f;

    for (int tz = 0; tz < 4; tz++) {
        const int iz = 2 * oz - 1 + tz;
        for (int ty = 0; ty < 4; ty++) {
            const int iy = 2 * oy - 1 + ty;
            __syncthreads();
            for (int i = threadIdx.x; i < 4 * CI * 8; i += 256) {
                int k  = i & 7;
                int ci = (i >> 3) % CI;
                int tx = i / (8 * CI);
                sw[i] = wT[((tz * 16 + ty * 4 + tx) * CI + ci) * CO + co0 + k];
            }
            __syncthreads();
            if ((unsigned)iz < DI && (unsigned)iy < DI) {
                const float* xbase = x + b * CI * DI3 + iz * DI2 + iy * DI;
#pragma unroll
                for (int tx = 0; tx < 4; tx++) {
                    const int ix = 2 * ox - 1 + tx;
                    if ((unsigned)ix < DI) {
                        const float* xp = xbase + ix;
                        const float* wp = sw + tx * (8 * CI);
#pragma unroll 4
                        for (int ci = 0; ci < CI; ci++) {
                            float xv = __ldg(xp); xp += DI3;
                            float4 wa = *reinterpret_cast<const float4*>(wp);
                            float4 wb = *reinterpret_cast<const float4*>(wp + 4);
                            wp += 8;
                            acc[0] = fmaf(xv, wa.x, acc[0]);
                            acc[1] = fmaf(xv, wa.y, acc[1]);
                            acc[2] = fmaf(xv, wa.z, acc[2]);
                            acc[3] = fmaf(xv, wa.w, acc[3]);
                            acc[4] = fmaf(xv, wb.x, acc[4]);
                            acc[5] = fmaf(xv, wb.y, acc[5]);
                            acc[6] = fmaf(xv, wb.z, acc[6]);
                            acc[7] = fmaf(xv, wb.w, acc[7]);
                        }
                    }
                }
            }
        }
    }

    const float m2 = mo[v];
    float zs[8];
#pragma unroll
    for (int k = 0; k < 8; k++) {
        float y = (acc[k] + __ldg(&bias[co0 + k])) * m2;
        zs[k] = y >= 0.f ? y : 0.01f * y;
        z[(b * CO + co0 + k) * DO3 + r] = zs[k];
    }
    if (threadIdx.x < 8) { ssum[threadIdx.x] = 0.f; ssq[threadIdx.x] = 0.f; }
    __syncthreads();
#pragma unroll
    for (int k = 0; k < 8; k++) {
        float s = zs[k], q = zs[k] * zs[k];
        for (int o = 16; o; o >>= 1) {
            s += __shfl_xor_sync(0xffffffffu, s, o);
            q += __shfl_xor_sync(0xffffffffu, q, o);
        }
        if ((threadIdx.x & 31) == 0) { atomicAdd(&ssum[k], s); atomicAdd(&ssq[k], q); }
    }
    __syncthreads();
    if (threadIdx.x < 8)
        atomicAdd(&stats[co0 + threadIdx.x], ssum[threadIdx.x]);
    else if (threadIdx.x < 16)
        atomicAdd(&stats[CO + co0 + threadIdx.x - 8], ssq[threadIdx.x - 8]);
}

// ---------------------------------------------------------------------------
// Transpose conv k=4 s=2 p=1 via parity decomposition (blockIdx.z = parity
// class). Output o: tap = o - 2i + 1. Uniform taps per class -> coalesced x.
// ---------------------------------------------------------------------------
template <int CI, int CO, int DI>
__global__ void __launch_bounds__(256) k_conv_t(
    const float* __restrict__ x, const float* __restrict__ wT,
    const float* __restrict__ bias, const float* __restrict__ mo,
    float* __restrict__ z, float* __restrict__ stats) {
    const int DO = 2 * DI, DI2 = DI * DI, DI3 = DI * DI * DI, DO3 = DO * DO * DO;
    __shared__ __align__(16) float sw[8 * CI * 8];
    __shared__ float ssum[8], ssq[8];
    const int cls = blockIdx.z;
    const int pz = (cls >> 2) & 1, py = (cls >> 1) & 1, px = cls & 1;
    const int co0 = blockIdx.y * 8;

    for (int i = threadIdx.x; i < 8 * CI * 8; i += 256) {
        int k  = i & 7;
        int ci = (i >> 3) % CI;
        int j  = i / (8 * CI);
        int jz = (j >> 2) & 1, jy = (j >> 1) & 1, jx = j & 1;
        int tz = pz ? 2 - 2 * jz : 1 + 2 * jz;
        int ty = py ? 2 - 2 * jy : 1 + 2 * jy;
        int tx = px ? 2 - 2 * jx : 1 + 2 * jx;
        sw[i] = wT[((tz * 16 + ty * 4 + tx) * CI + ci) * CO + co0 + k];
    }
    __syncthreads();

    const int v = blockIdx.x * 256 + threadIdx.x;
    const int b = v / DI3, r = v % DI3;
    const int zi = r / DI2, yi = (r / DI) % DI, xi = r % DI;
    float acc[8];
#pragma unroll
    for (int k = 0; k < 8; k++) acc[k] = 0.f;

#pragma unroll
    for (int jz = 0; jz < 2; jz++) {
        const int iz = pz ? zi + jz : zi - jz;
        if ((unsigned)iz >= DI) continue;
#pragma unroll
        for (int jy = 0; jy < 2; jy++) {
            const int iy = py ? yi + jy : yi - jy;
            if ((unsigned)iy >= DI) continue;
#pragma unroll
            for (int jx = 0; jx < 2; jx++) {
                const int ix = px ? xi + jx : xi - jx;
                if ((unsigned)ix >= DI) continue;
                const float* xp = x + b * CI * DI3 + iz * DI2 + iy * DI + ix;
                const float* wp = sw + (jz * 4 + jy * 2 + jx) * (8 * CI);
#pragma unroll 4
                for (int ci = 0; ci < CI; ci++) {
                    float xv = __ldg(xp); xp += DI3;
                    float4 wa = *reinterpret_cast<const float4*>(wp);
                    float4 wb = *reinterpret_cast<const float4*>(wp + 4);
                    wp += 8;
                    acc[0] = fmaf(xv, wa.x, acc[0]);
                    acc[1] = fmaf(xv, wa.y, acc[1]);
                    acc[2] = fmaf(xv, wa.z, acc[2]);
                    acc[3] = fmaf(xv, wa.w, acc[3]);
                    acc[4] = fmaf(xv, wb.x, acc[4]);
                    acc[5] = fmaf(xv, wb.y, acc[5]);
                    acc[6] = fmaf(xv, wb.z, acc[6]);
                    acc[7] = fmaf(xv, wb.w, acc[7]);
                }
            }
        }
    }

    const int oz = 2 * zi + pz, oy = 2 * yi + py, ox = 2 * xi + px;
    const int ro = (oz * DO + oy) * DO + ox;
    const float m2 = mo[b * DO3 + ro];
    float zs[8];
#pragma unroll
    for (int k = 0; k < 8; k++) {
        float y = (acc[k] + __ldg(&bias[co0 + k])) * m2;
        zs[k] = y >= 0.f ? y : 0.01f * y;
        z[(b * CO + co0 + k) * DO3 + ro] = zs[k];
    }
    if (threadIdx.x < 8) { ssum[threadIdx.x] = 0.f; ssq[threadIdx.x] = 0.f; }
    __syncthreads();
#pragma unroll
    for (int k = 0; k < 8; k++) {
        float s = zs[k], q = zs[k] * zs[k];
        for (int o = 16; o; o >>= 1) {
            s += __shfl_xor_sync(0xffffffffu, s, o);
            q += __shfl_xor_sync(0xffffffffu, q, o);
        }
        if ((threadIdx.x & 31) == 0) { atomicAdd(&ssum[k], s); atomicAdd(&ssq[k], q); }
    }
    __syncthreads();
    if (threadIdx.x < 8)
        atomicAdd(&stats[co0 + threadIdx.x], ssum[threadIdx.x]);
    else if (threadIdx.x < 16)
        atomicAdd(&stats[CO + co0 + threadIdx.x - 8], ssq[threadIdx.x - 8]);
}

// ---------------------------------------------------------------------------
// BN finalize: fold (mean, var, gamma, beta) into per-channel scale/shift
// ---------------------------------------------------------------------------
__global__ void k_finalize(const float* __restrict__ stats, const float* __restrict__ g,
                           const float* __restrict__ be, float* __restrict__ scale,
                           float* __restrict__ shift, int CO) {
    int c = threadIdx.x;
    if (c >= CO) return;
    float cnt  = fmaxf(stats[2 * CO], 1.f);
    float mean = stats[c] / cnt;
    float var  = stats[CO + c] / cnt - mean * mean;
    float s = g[c] * rsqrtf(var + 1e-5f);
    scale[c] = s;
    shift[c] = be[c] - mean * s;
}

// z = (z*scale[c] + shift[c]) * m[voxel]
__global__ void k_norm(float* __restrict__ z, const float* __restrict__ mo,
                       const float* __restrict__ scale, const float* __restrict__ shift,
                       int CO, int D3) {
    int idx = blockIdx.x * 256 + threadIdx.x;
    int c = (idx / D3) % CO;
    int b = idx / (D3 * CO);
    int r = idx % D3;
    z[idx] = fmaf(z[idx], scale[c], shift[c]) * mo[b * D3 + r];
}

// ---------------------------------------------------------------------------
// Head: dense 1x1x1 conv 64->32, bias everywhere
// ---------------------------------------------------------------------------
__global__ void __launch_bounds__(256) k_head(const float* __restrict__ x,
                                              const float* __restrict__ fwT,
                                              const float* __restrict__ fb,
                                              float* __restrict__ out) {
    __shared__ __align__(16) float sw[64 * 32];
    for (int i = threadIdx.x; i < 2048; i += 256) sw[i] = fwT[i];
    __syncthreads();
    const int D3 = 32768;
    int v = blockIdx.x * 256 + threadIdx.x;
    int b = v / D3, r = v % D3;
    float acc[32];
#pragma unroll
    for (int k = 0; k < 32; k++) acc[k] = 0.f;
    const float* xp = x + b * 64 * D3 + r;
#pragma unroll 2
    for (int ci = 0; ci < 64; ci++) {
        float xv = __ldg(xp); xp += D3;
        const float4* w4 = reinterpret_cast<const float4*>(sw + ci * 32);
#pragma unroll
        for (int q = 0; q < 8; q++) {
            float4 w = w4[q];
            acc[4 * q + 0] = fmaf(xv, w.x, acc[4 * q + 0]);
            acc[4 * q + 1] = fmaf(xv, w.y, acc[4 * q + 1]);
            acc[4 * q + 2] = fmaf(xv, w.z, acc[4 * q + 2]);
            acc[4 * q + 3] = fmaf(xv, w.w, acc[4 * q + 3]);
        }
    }
#pragma unroll
    for (int k = 0; k < 32; k++)
        out[(b * 32 + k) * D3 + r] = acc[k] + __ldg(&fb[k]);
}

// ---------------------------------------------------------------------------
// Host launcher
// ---------------------------------------------------------------------------
extern "C" void kernel_launch(void* const* d_in, const int* in_sizes, int n_in,
                              void* d_out, int out_size) {
    (void)in_sizes; (void)n_in; (void)out_size;
    float* S = nullptr;
    cudaGetSymbolAddress((void**)&S, g_scratch);

    const float* feat = (const float*)d_in[0];
    const float* mask = (const float*)d_in[1];
    const float* w1  = (const float*)d_in[2];  const float* b1  = (const float*)d_in[3];
    const float* g1  = (const float*)d_in[4];  const float* be1 = (const float*)d_in[5];
    const float* w2  = (const float*)d_in[6];  const float* b2  = (const float*)d_in[7];
    const float* g2  = (const float*)d_in[8];  const float* be2 = (const float*)d_in[9];
    const float* w3  = (const float*)d_in[10]; const float* b3  = (const float*)d_in[11];
    const float* g3  = (const float*)d_in[12]; const float* be3 = (const float*)d_in[13];
    const float* tw1 = (const float*)d_in[14]; const float* tb1 = (const float*)d_in[15];
    const float* tg1 = (const float*)d_in[16]; const float* tbe1= (const float*)d_in[17];
    const float* tw2 = (const float*)d_in[18]; const float* tb2 = (const float*)d_in[19];
    const float* tg2 = (const float*)d_in[20]; const float* tbe2= (const float*)d_in[21];
    const float* fw  = (const float*)d_in[22]; const float* fb  = (const float*)d_in[23];
    float* out = (float*)d_out;

    float *x0 = S+OX0, *z1 = S+OZ1, *z2 = S+OZ2, *z3 = S+OZ3, *z4 = S+OZ4, *z5 = S+OZ5;
    float *m0 = S+OM0, *m1 = S+OM1, *m2 = S+OM2, *m3 = S+OM3, *m4 = S+OM4, *m5 = S+OM5;
    float *w1T = S+OW1, *w2T = S+OW2, *w3T = S+OW3, *tw1T = S+OTW1, *tw2T = S+OTW2, *fwT = S+OFW;
    float *st = S+OST, *sc = S+OSC, *sh = S+OSH;

    k_zero<<<6, 256>>>(st, 5 * 260);
    k_pre<<<2048, 256>>>(feat, mask, x0, m0);
    k_transpose<<<32,   256>>>(w1,  w1T,  4,   32);
    k_transpose<<<512,  256>>>(w2,  w2T,  32,  64);
    k_transpose<<<2048, 256>>>(w3,  w3T,  64,  128);
    k_transpose<<<4096, 256>>>(tw1, tw1T, 128, 128);
    k_transpose<<<2048, 256>>>(tw2, tw2T, 128, 64);
    k_transpose_head<<<8, 256>>>(fw, fwT);

    // stage 1: 4 -> 32, 64^3 -> 32^3
    k_maskd_fwd<64, 32><<<256, 256>>>(m0, m1, st + 0 * 260 + 64);
    k_conv_fwd<4, 32, 64, 32><<<dim3(256, 4), 256>>>(x0, w1T, b1, m1, z1, st + 0 * 260);
    k_finalize<<<1, 128>>>(st + 0 * 260, g1, be1, sc + 0, sh + 0, 32);
    k_norm<<<8192, 256>>>(z1, m1, sc + 0, sh + 0, 32, 32768);

    // stage 2: 32 -> 64, 32^3 -> 16^3
    k_maskd_fwd<32, 16><<<32, 256>>>(m1, m2, st + 1 * 260 + 128);
    k_conv_fwd<32, 64, 32, 16><<<dim3(32, 8), 256>>>(z1, w2T, b2, m2, z2, st + 1 * 260);
    k_finalize<<<1, 128>>>(st + 1 * 260, g2, be2, sc + 128, sh + 128, 64);
    k_norm<<<2048, 256>>>(z2, m2, sc + 128, sh + 128, 64, 4096);

    // stage 3: 64 -> 128, 16^3 -> 8^3
    k_maskd_fwd<16, 8><<<4, 256>>>(m2, m3, st + 2 * 260 + 256);
    k_conv_fwd<64, 128, 16, 8><<<dim3(4, 16), 256>>>(z2, w3T, b3, m3, z3, st + 2 * 260);
    k_finalize<<<1, 128>>>(st + 2 * 260, g3, be3, sc + 256, sh + 256, 128);
    k_norm<<<512, 256>>>(z3, m3, sc + 256, sh + 256, 128, 512);

    // stage 4: tconv 128 -> 128, 8^3 -> 16^3
    k_maskd_t<8, 16><<<32, 256>>>(m3, m4, st + 3 * 260 + 256);
    k_conv_t<128, 128, 8><<<dim3(4, 16, 8), 256>>>(z3, tw1T, tb1, m4, z4, st + 3 * 260);
    k_finalize<<<1, 128>>>(st + 3 * 260, tg1, tbe1, sc + 384, sh + 384, 128);
    k_norm<<<4096, 256>>>(z4, m4, sc + 384, sh + 384, 128, 4096);

    // stage 5: tconv 128 -> 64, 16^3 -> 32^3
    k_maskd_t<16, 32><<<256, 256>>>(m4, m5, st + 4 * 260 + 128);
    k_conv_t<128, 64, 16><<<dim3(32, 8, 8), 256>>>(z4, tw2T, tb2, m5, z5, st + 4 * 260);
    k_finalize<<<1, 128>>>(st + 4 * 260, tg2, tbe2, sc + 512, sh + 512, 64);
    k_norm<<<16384, 256>>>(z5, m5, sc + 512, sh + 512, 64, 32768);

    // head: 64 -> 32, 32^3, dense
    k_head<<<256, 256>>>(z5, fwT, fb, out);
}

// round 4
// speedup vs baseline: 1.0896x; 1.0896x over previous
#include <cuda_runtime.h>
#include <math.h>

// ---------------------------------------------------------------------------
// Scratch arena (no allocations allowed -> __device__ global). Offsets in floats.
// ---------------------------------------------------------------------------
constexpr int OX0  = 0;          // 2*4*64^3
constexpr int OZ1  = 2097152;    // 2*32*32^3
constexpr int OZ2  = 4194304;    // 2*64*16^3
constexpr int OZ3  = 4718592;    // 2*128*8^3
constexpr int OZ4  = 4849664;    // 2*128*16^3
constexpr int OZ5  = 5898240;    // 2*64*32^3
constexpr int OM0  = 10092544;   // 2*64^3
constexpr int OM1  = 10616832;   // 2*32^3
constexpr int OM2  = 10682368;   // 2*16^3
constexpr int OM3  = 10690560;   // 2*8^3
constexpr int OM4  = 10691584;   // 2*16^3
constexpr int OM5  = 10699776;   // 2*32^3
constexpr int OW1  = 10765312;   // 32*4*64
constexpr int OW2  = 10773504;   // 64*32*64
constexpr int OW3  = 10904576;   // 128*64*64
constexpr int OTW1 = 11428864;   // 128*128*64
constexpr int OTW2 = 12477440;   // 64*128*64
constexpr int OFW  = 13001728;   // 64*32
constexpr int OST  = 13003776;   // 5*260 stats (sum[CO], sumsq[CO], cnt)
constexpr int OSC  = 13005076;   // 5*128 scale
constexpr int OSH  = 13005716;   // 5*128 shift
constexpr int TOT_SCRATCH = 13006848;

__device__ float g_scratch[TOT_SCRATCH];

// ---------------------------------------------------------------------------
// Packed f32x2 helpers (sm_103a; ptxas never auto-fuses FFMA2 from C++)
// ---------------------------------------------------------------------------
typedef unsigned long long u64;

__device__ __forceinline__ u64 pack2(float v) {
    u64 r;
    asm("mov.b64 %0, {%1, %1};" : "=l"(r) : "f"(v));
    return r;
}
__device__ __forceinline__ u64 ffma2(u64 a, u64 b, u64 c) {
    u64 d;
    asm("fma.rn.f32x2 %0, %1, %2, %3;" : "=l"(d) : "l"(a), "l"(b), "l"(c));
    return d;
}
__device__ __forceinline__ float2 unpack2(u64 a) {
    float2 f;
    asm("mov.b64 {%0, %1}, %2;" : "=f"(f.x), "=f"(f.y) : "l"(a));
    return f;
}

// ---------------------------------------------------------------------------
// Small utility kernels
// ---------------------------------------------------------------------------
__global__ void k_zero(float* __restrict__ p, int n) {
    int i = blockIdx.x * 256 + threadIdx.x;
    if (i < n) p[i] = 0.f;
}

__global__ void k_pre(const float* __restrict__ feat, const float* __restrict__ mask,
                      float* __restrict__ x0, float* __restrict__ m0) {
    int v = blockIdx.x * 256 + threadIdx.x;
    float m = mask[v] > 0.5f ? 1.f : 0.f;
    m0[v] = m;
    int b = v >> 18;
    int r = v & 262143;
#pragma unroll
    for (int c = 0; c < 4; c++)
        x0[(b * 4 + c) * 262144 + r] = feat[(b * 4 + c) * 262144 + r] * m;
}

// wT[(t*CI+ci)*CO+co] = w[(co*CI+ci)*64+t]
__global__ void k_transpose(const float* __restrict__ w, float* __restrict__ wT,
                            int CI, int CO) {
    int idx = blockIdx.x * 256 + threadIdx.x;
    if (idx >= CO * CI * 64) return;
    int t  = idx & 63;
    int ci = (idx >> 6) % CI;
    int co = idx / (64 * CI);
    wT[(t * CI + ci) * CO + co] = w[idx];
}

__global__ void k_transpose_head(const float* __restrict__ fw, float* __restrict__ fwT) {
    int idx = blockIdx.x * 256 + threadIdx.x;
    if (idx >= 2048) return;
    int co = idx / 64;
    int ci = idx % 64;
    fwT[ci * 32 + co] = fw[idx];
}

// ---------------------------------------------------------------------------
// Mask dilation kernels (+ active count)
// ---------------------------------------------------------------------------
template <int DI, int DO>
__global__ void k_maskd_fwd(const float* __restrict__ mi, float* __restrict__ mo,
                            float* __restrict__ cnt) {
    const int DO3 = DO * DO * DO, DI2 = DI * DI, DI3 = DI * DI * DI;
    int v = blockIdx.x * 256 + threadIdx.x;
    int b = v / DO3, r = v % DO3;
    int oz = r / (DO * DO), oy = (r / DO) % DO, ox = r % DO;
    float m = 0.f;
    for (int tz = 0; tz < 4; tz++) {
        int iz = 2 * oz - 1 + tz;
        if ((unsigned)iz >= DI) continue;
        for (int ty = 0; ty < 4; ty++) {
            int iy = 2 * oy - 1 + ty;
            if ((unsigned)iy >= DI) continue;
            const float* p = mi + b * DI3 + iz * DI2 + iy * DI;
            for (int tx = 0; tx < 4; tx++) {
                int ix = 2 * ox - 1 + tx;
                if ((unsigned)ix < DI) m += p[ix];
            }
        }
    }
    float act = m > 0.f ? 1.f : 0.f;
    mo[v] = act;
    float s = act;
    for (int o = 16; o; o >>= 1) s += __shfl_xor_sync(0xffffffffu, s, o);
    if ((threadIdx.x & 31) == 0) atomicAdd(cnt, s);
}

template <int DI, int DO>
__global__ void k_maskd_t(const float* __restrict__ mi, float* __restrict__ mo,
                          float* __restrict__ cnt) {
    const int DO3 = DO * DO * DO, DI2 = DI * DI, DI3 = DI * DI * DI;
    int v = blockIdx.x * 256 + threadIdx.x;
    int b = v / DO3, r = v % DO3;
    int oz = r / (DO * DO), oy = (r / DO) % DO, ox = r % DO;
    int izl[2], iyl[2], ixl[2];
    izl[0] = oz >> 1; izl[1] = (oz & 1) ? (oz >> 1) + 1 : (oz >> 1) - 1;
    iyl[0] = oy >> 1; iyl[1] = (oy & 1) ? (oy >> 1) + 1 : (oy >> 1) - 1;
    ixl[0] = ox >> 1; ixl[1] = (ox & 1) ? (ox >> 1) + 1 : (ox >> 1) - 1;
    float m = 0.f;
#pragma unroll
    for (int jz = 0; jz < 2; jz++) {
        int iz = izl[jz];
        if ((unsigned)iz >= DI) continue;
#pragma unroll
        for (int jy = 0; jy < 2; jy++) {
            int iy = iyl[jy];
            if ((unsigned)iy >= DI) continue;
#pragma unroll
            for (int jx = 0; jx < 2; jx++) {
                int ix = ixl[jx];
                if ((unsigned)ix < DI) m += mi[b * DI3 + iz * DI2 + iy * DI + ix];
            }
        }
    }
    float act = m > 0.f ? 1.f : 0.f;
    mo[v] = act;
    float s = act;
    for (int o = 16; o; o >>= 1) s += __shfl_xor_sync(0xffffffffu, s, o);
    if ((threadIdx.x & 31) == 0) atomicAdd(cnt, s);
}

// ---------------------------------------------------------------------------
// Forward conv k=4 s=2 p=1, + bias, * dilated mask, LeakyReLU, stats.
// Thread = 1 output voxel x 8 consecutive co (4 packed f32x2 accumulators).
// FULLW: stage all 64 taps once (small CI); else per-(tz,ty) slab staging.
// ---------------------------------------------------------------------------
template <int CI, int CO, int DI, int DO, bool FULLW, int NT>
__global__ void __launch_bounds__(NT) k_conv_fwd(
    const float* __restrict__ x, const float* __restrict__ wT,
    const float* __restrict__ bias, const float* __restrict__ mo,
    float* __restrict__ z, float* __restrict__ stats) {
    constexpr int SWSZ = FULLW ? 64 * CI * 8 : 4 * CI * 8;
    __shared__ __align__(16) float sw[SWSZ];
    __shared__ float ssum[8], ssq[8];
    const int DO3 = DO * DO * DO, DI3 = DI * DI * DI, DI2 = DI * DI;
    const int co0 = blockIdx.y * 8;
    const int v = blockIdx.x * NT + threadIdx.x;
    const int b = v / DO3, r = v % DO3;
    const int oz = r / (DO * DO), oy = (r / DO) % DO, ox = r % DO;
    u64 acc2[4] = {0ull, 0ull, 0ull, 0ull};

    if (FULLW) {
        for (int i = threadIdx.x; i < 64 * CI * 8; i += NT) {
            int k  = i & 7;
            int ci = (i >> 3) % CI;
            int t  = i / (8 * CI);
            sw[i] = wT[(t * CI + ci) * CO + co0 + k];
        }
        __syncthreads();
    }

    for (int tz = 0; tz < 4; tz++) {
        const int iz = 2 * oz - 1 + tz;
        for (int ty = 0; ty < 4; ty++) {
            const int iy = 2 * oy - 1 + ty;
            if (!FULLW) {
                __syncthreads();
                for (int i = threadIdx.x; i < 4 * CI * 8; i += NT) {
                    int k  = i & 7;
                    int ci = (i >> 3) % CI;
                    int tx = i / (8 * CI);
                    sw[i] = wT[((tz * 16 + ty * 4 + tx) * CI + ci) * CO + co0 + k];
                }
                __syncthreads();
            }
            if ((unsigned)iz < DI && (unsigned)iy < DI) {
                const float* xbase = x + b * CI * DI3 + iz * DI2 + iy * DI;
#pragma unroll
                for (int tx = 0; tx < 4; tx++) {
                    const int ix = 2 * ox - 1 + tx;
                    if ((unsigned)ix < DI) {
                        const float* xp = xbase + ix;
                        const float* wp = FULLW
                            ? sw + (tz * 16 + ty * 4 + tx) * (8 * CI)
                            : sw + tx * (8 * CI);
#pragma unroll 4
                        for (int ci = 0; ci < CI; ci++) {
                            u64 xv = pack2(__ldg(xp)); xp += DI3;
                            ulonglong2 wa = *reinterpret_cast<const ulonglong2*>(wp);
                            ulonglong2 wb = *reinterpret_cast<const ulonglong2*>(wp + 4);
                            wp += 8;
                            acc2[0] = ffma2(xv, wa.x, acc2[0]);
                            acc2[1] = ffma2(xv, wa.y, acc2[1]);
                            acc2[2] = ffma2(xv, wb.x, acc2[2]);
                            acc2[3] = ffma2(xv, wb.y, acc2[3]);
                        }
                    }
                }
            }
        }
    }

    const float m2 = mo[v];
    float zs[8];
#pragma unroll
    for (int p = 0; p < 4; p++) {
        float2 a = unpack2(acc2[p]);
        float y0 = (a.x + __ldg(&bias[co0 + 2 * p])) * m2;
        float y1 = (a.y + __ldg(&bias[co0 + 2 * p + 1])) * m2;
        zs[2 * p]     = y0 >= 0.f ? y0 : 0.01f * y0;
        zs[2 * p + 1] = y1 >= 0.f ? y1 : 0.01f * y1;
        z[(b * CO + co0 + 2 * p)     * DO3 + r] = zs[2 * p];
        z[(b * CO + co0 + 2 * p + 1) * DO3 + r] = zs[2 * p + 1];
    }
    if (!FULLW) __syncthreads();
    if (threadIdx.x < 8) { ssum[threadIdx.x] = 0.f; ssq[threadIdx.x] = 0.f; }
    __syncthreads();
#pragma unroll
    for (int k = 0; k < 8; k++) {
        float s = zs[k], q = zs[k] * zs[k];
        for (int o = 16; o; o >>= 1) {
            s += __shfl_xor_sync(0xffffffffu, s, o);
            q += __shfl_xor_sync(0xffffffffu, q, o);
        }
        if ((threadIdx.x & 31) == 0) { atomicAdd(&ssum[k], s); atomicAdd(&ssq[k], q); }
    }
    __syncthreads();
    if (threadIdx.x < 8)
        atomicAdd(&stats[co0 + threadIdx.x], ssum[threadIdx.x]);
    else if (threadIdx.x < 16)
        atomicAdd(&stats[CO + co0 + threadIdx.x - 8], ssq[threadIdx.x - 8]);
}

// ---------------------------------------------------------------------------
// Transpose conv k=4 s=2 p=1 via parity decomposition (blockIdx.z = class).
// Packed f32x2 over co pairs.
// ---------------------------------------------------------------------------
template <int CI, int CO, int DI>
__global__ void __launch_bounds__(256) k_conv_t(
    const float* __restrict__ x, const float* __restrict__ wT,
    const float* __restrict__ bias, const float* __restrict__ mo,
    float* __restrict__ z, float* __restrict__ stats) {
    const int DO = 2 * DI, DI2 = DI * DI, DI3 = DI * DI * DI, DO3 = DO * DO * DO;
    __shared__ __align__(16) float sw[8 * CI * 8];
    __shared__ float ssum[8], ssq[8];
    const int cls = blockIdx.z;
    const int pz = (cls >> 2) & 1, py = (cls >> 1) & 1, px = cls & 1;
    const int co0 = blockIdx.y * 8;

    for (int i = threadIdx.x; i < 8 * CI * 8; i += 256) {
        int k  = i & 7;
        int ci = (i >> 3) % CI;
        int j  = i / (8 * CI);
        int jz = (j >> 2) & 1, jy = (j >> 1) & 1, jx = j & 1;
        int tz = pz ? 2 - 2 * jz : 1 + 2 * jz;
        int ty = py ? 2 - 2 * jy : 1 + 2 * jy;
        int tx = px ? 2 - 2 * jx : 1 + 2 * jx;
        sw[i] = wT[((tz * 16 + ty * 4 + tx) * CI + ci) * CO + co0 + k];
    }
    __syncthreads();

    const int v = blockIdx.x * 256 + threadIdx.x;
    const int b = v / DI3, r = v % DI3;
    const int zi = r / DI2, yi = (r / DI) % DI, xi = r % DI;
    u64 acc2[4] = {0ull, 0ull, 0ull, 0ull};

#pragma unroll
    for (int jz = 0; jz < 2; jz++) {
        const int iz = pz ? zi + jz : zi - jz;
        if ((unsigned)iz >= DI) continue;
#pragma unroll
        for (int jy = 0; jy < 2; jy++) {
            const int iy = py ? yi + jy : yi - jy;
            if ((unsigned)iy >= DI) continue;
#pragma unroll
            for (int jx = 0; jx < 2; jx++) {
                const int ix = px ? xi + jx : xi - jx;
                if ((unsigned)ix >= DI) continue;
                const float* xp = x + b * CI * DI3 + iz * DI2 + iy * DI + ix;
                const float* wp = sw + (jz * 4 + jy * 2 + jx) * (8 * CI);
#pragma unroll 4
                for (int ci = 0; ci < CI; ci++) {
                    u64 xv = pack2(__ldg(xp)); xp += DI3;
                    ulonglong2 wa = *reinterpret_cast<const ulonglong2*>(wp);
                    ulonglong2 wb = *reinterpret_cast<const ulonglong2*>(wp + 4);
                    wp += 8;
                    acc2[0] = ffma2(xv, wa.x, acc2[0]);
                    acc2[1] = ffma2(xv, wa.y, acc2[1]);
                    acc2[2] = ffma2(xv, wb.x, acc2[2]);
                    acc2[3] = ffma2(xv, wb.y, acc2[3]);
                }
            }
        }
    }

    const int oz = 2 * zi + pz, oy = 2 * yi + py, ox = 2 * xi + px;
    const int ro = (oz * DO + oy) * DO + ox;
    const float m2 = mo[b * DO3 + ro];
    float zs[8];
#pragma unroll
    for (int p = 0; p < 4; p++) {
        float2 a = unpack2(acc2[p]);
        float y0 = (a.x + __ldg(&bias[co0 + 2 * p])) * m2;
        float y1 = (a.y + __ldg(&bias[co0 + 2 * p + 1])) * m2;
        zs[2 * p]     = y0 >= 0.f ? y0 : 0.01f * y0;
        zs[2 * p + 1] = y1 >= 0.f ? y1 : 0.01f * y1;
        z[(b * CO + co0 + 2 * p)     * DO3 + ro] = zs[2 * p];
        z[(b * CO + co0 + 2 * p + 1) * DO3 + ro] = zs[2 * p + 1];
    }
    if (threadIdx.x < 8) { ssum[threadIdx.x] = 0.f; ssq[threadIdx.x] = 0.f; }
    __syncthreads();
#pragma unroll
    for (int k = 0; k < 8; k++) {
        float s = zs[k], q = zs[k] * zs[k];
        for (int o = 16; o; o >>= 1) {
            s += __shfl_xor_sync(0xffffffffu, s, o);
            q += __shfl_xor_sync(0xffffffffu, q, o);
        }
        if ((threadIdx.x & 31) == 0) { atomicAdd(&ssum[k], s); atomicAdd(&ssq[k], q); }
    }
    __syncthreads();
    if (threadIdx.x < 8)
        atomicAdd(&stats[co0 + threadIdx.x], ssum[threadIdx.x]);
    else if (threadIdx.x < 16)
        atomicAdd(&stats[CO + co0 + threadIdx.x - 8], ssq[threadIdx.x - 8]);
}

// ---------------------------------------------------------------------------
// BN finalize + apply
// ---------------------------------------------------------------------------
__global__ void k_finalize(const float* __restrict__ stats, const float* __restrict__ g,
                           const float* __restrict__ be, float* __restrict__ scale,
                           float* __restrict__ shift, int CO) {
    int c = threadIdx.x;
    if (c >= CO) return;
    float cnt  = fmaxf(stats[2 * CO], 1.f);
    float mean = stats[c] / cnt;
    float var  = stats[CO + c] / cnt - mean * mean;
    float s = g[c] * rsqrtf(var + 1e-5f);
    scale[c] = s;
    shift[c] = be[c] - mean * s;
}

__global__ void k_norm(float* __restrict__ z, const float* __restrict__ mo,
                       const float* __restrict__ scale, const float* __restrict__ shift,
                       int CO, int D3) {
    int idx = blockIdx.x * 256 + threadIdx.x;
    int c = (idx / D3) % CO;
    int b = idx / (D3 * CO);
    int r = idx % D3;
    z[idx] = fmaf(z[idx], scale[c], shift[c]) * mo[b * D3 + r];
}

// ---------------------------------------------------------------------------
// Head: dense 1x1x1 conv 64->32 (packed f32x2)
// ---------------------------------------------------------------------------
__global__ void __launch_bounds__(256) k_head(const float* __restrict__ x,
                                              const float* __restrict__ fwT,
                                              const float* __restrict__ fb,
                                              float* __restrict__ out) {
    __shared__ __align__(16) float sw[64 * 32];
    for (int i = threadIdx.x; i < 2048; i += 256) sw[i] = fwT[i];
    __syncthreads();
    const int D3 = 32768;
    int v = blockIdx.x * 256 + threadIdx.x;
    int b = v / D3, r = v % D3;
    u64 acc2[16];
#pragma unroll
    for (int k = 0; k < 16; k++) acc2[k] = 0ull;
    const float* xp = x + b * 64 * D3 + r;
#pragma unroll 2
    for (int ci = 0; ci < 64; ci++) {
        u64 xv = pack2(__ldg(xp)); xp += D3;
        const ulonglong2* w2 = reinterpret_cast<const ulonglong2*>(sw + ci * 32);
#pragma unroll
        for (int q = 0; q < 8; q++) {
            ulonglong2 w = w2[q];
            acc2[2 * q]     = ffma2(xv, w.x, acc2[2 * q]);
            acc2[2 * q + 1] = ffma2(xv, w.y, acc2[2 * q + 1]);
        }
    }
#pragma unroll
    for (int k = 0; k < 16; k++) {
        float2 a = unpack2(acc2[k]);
        out[(b * 32 + 2 * k)     * D3 + r] = a.x + __ldg(&fb[2 * k]);
        out[(b * 32 + 2 * k + 1) * D3 + r] = a.y + __ldg(&fb[2 * k + 1]);
    }
}

// ---------------------------------------------------------------------------
// Host launcher
// ---------------------------------------------------------------------------
extern "C" void kernel_launch(void* const* d_in, const int* in_sizes, int n_in,
                              void* d_out, int out_size) {
    (void)in_sizes; (void)n_in; (void)out_size;
    float* S = nullptr;
    cudaGetSymbolAddress((void**)&S, g_scratch);

    const float* feat = (const float*)d_in[0];
    const float* mask = (const float*)d_in[1];
    const float* w1  = (const float*)d_in[2];  const float* b1  = (const float*)d_in[3];
    const float* g1  = (const float*)d_in[4];  const float* be1 = (const float*)d_in[5];
    const float* w2  = (const float*)d_in[6];  const float* b2  = (const float*)d_in[7];
    const float* g2  = (const float*)d_in[8];  const float* be2 = (const float*)d_in[9];
    const float* w3  = (const float*)d_in[10]; const float* b3  = (const float*)d_in[11];
    const float* g3  = (const float*)d_in[12]; const float* be3 = (const float*)d_in[13];
    const float* tw1 = (const float*)d_in[14]; const float* tb1 = (const float*)d_in[15];
    const float* tg1 = (const float*)d_in[16]; const float* tbe1= (const float*)d_in[17];
    const float* tw2 = (const float*)d_in[18]; const float* tb2 = (const float*)d_in[19];
    const float* tg2 = (const float*)d_in[20]; const float* tbe2= (const float*)d_in[21];
    const float* fw  = (const float*)d_in[22]; const float* fb  = (const float*)d_in[23];
    float* out = (float*)d_out;

    float *x0 = S+OX0, *z1 = S+OZ1, *z2 = S+OZ2, *z3 = S+OZ3, *z4 = S+OZ4, *z5 = S+OZ5;
    float *m0 = S+OM0, *m1 = S+OM1, *m2 = S+OM2, *m3 = S+OM3, *m4 = S+OM4, *m5 = S+OM5;
    float *w1T = S+OW1, *w2T = S+OW2, *w3T = S+OW3, *tw1T = S+OTW1, *tw2T = S+OTW2, *fwT = S+OFW;
    float *st = S+OST, *sc = S+OSC, *sh = S+OSH;

    k_zero<<<6, 256>>>(st, 5 * 260);
    k_pre<<<2048, 256>>>(feat, mask, x0, m0);
    k_transpose<<<32,   256>>>(w1,  w1T,  4,   32);
    k_transpose<<<512,  256>>>(w2,  w2T,  32,  64);
    k_transpose<<<2048, 256>>>(w3,  w3T,  64,  128);
    k_transpose<<<4096, 256>>>(tw1, tw1T, 128, 128);
    k_transpose<<<2048, 256>>>(tw2, tw2T, 128, 64);
    k_transpose_head<<<8, 256>>>(fw, fwT);

    // stage 1: 4 -> 32, 64^3 -> 32^3  (full weight staging, no in-loop syncs)
    k_maskd_fwd<64, 32><<<256, 256>>>(m0, m1, st + 0 * 260 + 64);
    k_conv_fwd<4, 32, 64, 32, true, 256><<<dim3(256, 4), 256>>>(x0, w1T, b1, m1, z1, st + 0 * 260);
    k_finalize<<<1, 128>>>(st + 0 * 260, g1, be1, sc + 0, sh + 0, 32);
    k_norm<<<8192, 256>>>(z1, m1, sc + 0, sh + 0, 32, 32768);

    // stage 2: 32 -> 64, 32^3 -> 16^3
    k_maskd_fwd<32, 16><<<32, 256>>>(m1, m2, st + 1 * 260 + 128);
    k_conv_fwd<32, 64, 32, 16, false, 256><<<dim3(32, 8), 256>>>(z1, w2T, b2, m2, z2, st + 1 * 260);
    k_finalize<<<1, 128>>>(st + 1 * 260, g2, be2, sc + 128, sh + 128, 64);
    k_norm<<<2048, 256>>>(z2, m2, sc + 128, sh + 128, 64, 4096);

    // stage 3: 64 -> 128, 16^3 -> 8^3  (128-thread blocks -> 128 CTAs)
    k_maskd_fwd<16, 8><<<4, 256>>>(m2, m3, st + 2 * 260 + 256);
    k_conv_fwd<64, 128, 16, 8, false, 128><<<dim3(8, 16), 128>>>(z2, w3T, b3, m3, z3, st + 2 * 260);
    k_finalize<<<1, 128>>>(st + 2 * 260, g3, be3, sc + 256, sh + 256, 128);
    k_norm<<<512, 256>>>(z3, m3, sc + 256, sh + 256, 128, 512);

    // stage 4: tconv 128 -> 128, 8^3 -> 16^3
    k_maskd_t<8, 16><<<32, 256>>>(m3, m4, st + 3 * 260 + 256);
    k_conv_t<128, 128, 8><<<dim3(4, 16, 8), 256>>>(z3, tw1T, tb1, m4, z4, st + 3 * 260);
    k_finalize<<<1, 128>>>(st + 3 * 260, tg1, tbe1, sc + 384, sh + 384, 128);
    k_norm<<<4096, 256>>>(z4, m4, sc + 384, sh + 384, 128, 4096);

    // stage 5: tconv 128 -> 64, 16^3 -> 32^3
    k_maskd_t<16, 32><<<256, 256>>>(m4, m5, st + 4 * 260 + 128);
    k_conv_t<128, 64, 16><<<dim3(32, 8, 8), 256>>>(z4, tw2T, tb2, m5, z5, st + 4 * 260);
    k_finalize<<<1, 128>>>(st + 4 * 260, tg2, tbe2, sc + 512, sh + 512, 64);
    k_norm<<<16384, 256>>>(z5, m5, sc + 512, sh + 512, 64, 32768);

    // head: 64 -> 32, 32^3, dense
    k_head<<<256, 256>>>(z5, fwT, fb, out);
}